// round 3
// baseline (speedup 1.0000x reference)
#include <cuda_runtime.h>
#include <math.h>

// Problem constants
#define BB    4
#define CC    256
#define HWSZ  4096
#define CPG   8

// ---------------- scratch (device globals; no allocation allowed) ----------------
__device__ float g_a  [BB*CC*HWSZ];        // groupnorm(+silu) output
__device__ float g_h  [BB*CC*HWSZ];        // conv1 output
__device__ float g_xr [BB*CC*HWSZ];        // residual branch output
__device__ float g_qkv[BB*3*CC*HWSZ];      // qkv projections [b][3C][HW]
__device__ float g_ao [BB*CC*HWSZ];        // attention output [b][C][HW]
__device__ float g_gb [BB*2*CC];           // FiLM gamma/beta
__device__ float g_col[(size_t)BB*2304*HWSZ];     // im2col buffer
__device__ float g_S  [(size_t)BB*HWSZ*HWSZ];     // scores St[t][s] per batch
__device__ float g_rdx[BB*2*HWSZ];         // per-column max / invsum

// ---------------- GroupNorm (+ optional SiLU), float4 vectorized ----------------
// grid: B*32 blocks, 256 threads
__global__ void gn_kernel(const float* __restrict__ x, const float* __restrict__ sc,
                          const float* __restrict__ bi, float* __restrict__ y, int dosilu) {
    __shared__ float rs[256], rq[256];
    __shared__ float mv[2];
    int bg = blockIdx.x;
    int b = bg >> 5, g = bg & 31;
    const float4* xp = (const float4*)(x + (size_t)(b * CC + g * CPG) * HWSZ);
    float4* yp = (float4*)(y + (size_t)(b * CC + g * CPG) * HWSZ);
    int tid = threadIdx.x;
    float sum = 0.f, sq = 0.f;
    for (int i = tid; i < 8192; i += 256) {
        float4 v = xp[i];
        sum += v.x + v.y + v.z + v.w;
        sq += v.x*v.x + v.y*v.y + v.z*v.z + v.w*v.w;
    }
    rs[tid] = sum; rq[tid] = sq;
    __syncthreads();
    for (int st = 128; st > 0; st >>= 1) {
        if (tid < st) { rs[tid] += rs[tid + st]; rq[tid] += rq[tid + st]; }
        __syncthreads();
    }
    if (tid == 0) {
        float m = rs[0] * (1.f / 32768.f);
        float var = rq[0] * (1.f / 32768.f) - m * m;
        mv[0] = m; mv[1] = rsqrtf(var + 1e-5f);
    }
    __syncthreads();
    float m = mv[0], inv = mv[1];
    for (int i = tid; i < 8192; i += 256) {
        int c = g * CPG + (i >> 10);
        float a = inv * sc[c], bb = bi[c] - m * a;
        float4 v = xp[i];
        v.x = v.x * a + bb; v.y = v.y * a + bb; v.z = v.z * a + bb; v.w = v.w * a + bb;
        if (dosilu) {
            v.x = v.x / (1.f + __expf(-v.x));
            v.y = v.y / (1.f + __expf(-v.y));
            v.z = v.z / (1.f + __expf(-v.z));
            v.w = v.w / (1.f + __expf(-v.w));
        }
        yp[i] = v;
    }
}

// ---------------- im2col: col[b][ic*9+k][p] = x[b][ic][p shifted by k] ----------------
// grid (4, 2304, B), block 256, 4 px per thread
__global__ void im2col_kernel(const float* __restrict__ x, float* __restrict__ col) {
    int p = (blockIdx.x * 256 + threadIdx.x) * 4;
    int ck = blockIdx.y, b = blockIdx.z;
    int ic = ck / 9, k = ck - ic * 9;
    int kh = k / 3 - 1, kw = k - (k / 3) * 3 - 1;
    int h = p >> 6, w = p & 63;
    int h2 = h + kh;
    float4 v = make_float4(0.f, 0.f, 0.f, 0.f);
    if ((unsigned)h2 < 64u) {
        const float* base = x + ((size_t)(b * CC + ic) << 12) + (h2 << 6);
        float* ve = (float*)&v;
        #pragma unroll
        for (int e = 0; e < 4; e++) {
            int w2 = w + e + kw;
            if ((unsigned)w2 < 64u) ve[e] = base[w2];
        }
    }
    *(float4*)&col[(size_t)b * 2304 * HWSZ + (size_t)ck * HWSZ + p] = v;
}

// ---------------- FiLM mlp: gb[b,j] = silu(te[b,:]) . mlp_w[j,:] + mlp_b[j] ----------------
__global__ void film_mlp_kernel(const float* __restrict__ te, const float* __restrict__ w,
                                const float* __restrict__ bi, float* __restrict__ gb) {
    __shared__ float s_te[256];
    int b = blockIdx.x, tid = threadIdx.x;
    for (int i = tid; i < 256; i += 128) {
        float v = te[b * 256 + i];
        s_te[i] = v / (1.f + __expf(-v));
    }
    __syncthreads();
    int j = blockIdx.y * 128 + tid;
    const float* wr = w + (size_t)j * 256;
    float acc = bi[j];
    for (int t = 0; t < 256; t++) acc += s_te[t] * wr[t];
    gb[b * 512 + j] = acc;
}

// ---------------- generic 128x128 GEMM with fused epilogues ----------------
// Y[b][o][p] = alpha * sum_k A[o][k] (or A[k][o] if aCol) * X[b][k][p]
//   then + bias[o];   then film: (1+gamma[b,o])*v + beta[b,o];
//   then * cscale[b][p];   then + res[b][o][p]
// N fixed = 4096 (row stride of X, Y, res). K % 16 == 0, M % 128 == 0.
__global__ void __launch_bounds__(256, 2) gemm128_kernel(
    const float* __restrict__ A, const float* __restrict__ X, float* __restrict__ Y,
    int K, int aCol, int lda,
    long long strideA, long long strideX, long long strideY,
    const float* __restrict__ bias,
    const float* __restrict__ film,
    const float* __restrict__ res, long long strideRes,
    const float* __restrict__ cscale, long long strideCS,
    float alpha) {
    __shared__ float sA[2][16][132];
    __shared__ float sB[2][16][132];
    int b = blockIdx.z;
    const float* Ab = A + strideA * b;
    const float* Xb = X + strideX * b;
    float* Yb = Y + strideY * b;
    int o0 = blockIdx.y * 128, p0 = blockIdx.x * 128;
    int tid = threadIdx.x, tx = tid & 15, ty = tid >> 4;

    unsigned long long acc[8][4];
    #pragma unroll
    for (int i = 0; i < 8; i++)
        #pragma unroll
        for (int j = 0; j < 4; j++) acc[i][j] = 0ull;

    // initial tile (k0 = 0) into buffer 0
    if (aCol) {
        #pragma unroll
        for (int r = 0; r < 2; r++) {
            int f = tid + r * 256, kk = f >> 5, o4 = f & 31;
            float4 v = *(const float4*)&Ab[(size_t)kk * lda + o0 + o4 * 4];
            *(float4*)&sA[0][kk][o4 * 4] = v;
        }
    } else {
        #pragma unroll
        for (int r = 0; r < 2; r++) {
            int f = tid + r * 256, o = f >> 2, kq = f & 3;
            float4 v = *(const float4*)&Ab[(size_t)(o0 + o) * lda + kq * 4];
            sA[0][kq * 4 + 0][o] = v.x; sA[0][kq * 4 + 1][o] = v.y;
            sA[0][kq * 4 + 2][o] = v.z; sA[0][kq * 4 + 3][o] = v.w;
        }
    }
    #pragma unroll
    for (int r = 0; r < 2; r++) {
        int f = tid + r * 256, kk = f >> 5, p4 = f & 31;
        float4 v = *(const float4*)&Xb[(size_t)kk * 4096 + p0 + p4 * 4];
        *(float4*)&sB[0][kk][p4 * 4] = v;
    }
    __syncthreads();

    int nk = K >> 4;
    int cur = 0;
    for (int kt = 0; kt < nk; kt++) {
        float4 ra0, ra1, rb0, rb1;
        bool has = (kt + 1 < nk);
        int k0n = (kt + 1) << 4;
        if (has) {
            if (aCol) {
                { int f = tid;       int kk = f >> 5, o4 = f & 31; ra0 = *(const float4*)&Ab[(size_t)(k0n + kk) * lda + o0 + o4 * 4]; }
                { int f = tid + 256; int kk = f >> 5, o4 = f & 31; ra1 = *(const float4*)&Ab[(size_t)(k0n + kk) * lda + o0 + o4 * 4]; }
            } else {
                { int f = tid;       int o = f >> 2, kq = f & 3; ra0 = *(const float4*)&Ab[(size_t)(o0 + o) * lda + k0n + kq * 4]; }
                { int f = tid + 256; int o = f >> 2, kq = f & 3; ra1 = *(const float4*)&Ab[(size_t)(o0 + o) * lda + k0n + kq * 4]; }
            }
            { int f = tid;       int kk = f >> 5, p4 = f & 31; rb0 = *(const float4*)&Xb[(size_t)(k0n + kk) * 4096 + p0 + p4 * 4]; }
            { int f = tid + 256; int kk = f >> 5, p4 = f & 31; rb1 = *(const float4*)&Xb[(size_t)(k0n + kk) * 4096 + p0 + p4 * 4]; }
        }
        #pragma unroll
        for (int kk = 0; kk < 16; kk++) {
            float4 a0 = *(const float4*)&sA[cur][kk][ty * 8];
            float4 a1 = *(const float4*)&sA[cur][kk][ty * 8 + 4];
            ulonglong2 bl = *(const ulonglong2*)&sB[cur][kk][tx * 8];
            ulonglong2 bh = *(const ulonglong2*)&sB[cur][kk][tx * 8 + 4];
            unsigned long long bp[4] = { bl.x, bl.y, bh.x, bh.y };
            float av[8] = { a0.x, a0.y, a0.z, a0.w, a1.x, a1.y, a1.z, a1.w };
            #pragma unroll
            for (int i = 0; i < 8; i++) {
                unsigned long long ad;
                asm("mov.b64 %0, {%1, %2};" : "=l"(ad) : "f"(av[i]), "f"(av[i]));
                #pragma unroll
                for (int j = 0; j < 4; j++)
                    asm("fma.rn.f32x2 %0, %1, %2, %0;" : "+l"(acc[i][j]) : "l"(ad), "l"(bp[j]));
            }
        }
        if (has) {
            int nb = cur ^ 1;
            if (aCol) {
                { int f = tid;       int kk = f >> 5, o4 = f & 31; *(float4*)&sA[nb][kk][o4 * 4] = ra0; }
                { int f = tid + 256; int kk = f >> 5, o4 = f & 31; *(float4*)&sA[nb][kk][o4 * 4] = ra1; }
            } else {
                { int f = tid;       int o = f >> 2, kq = f & 3;
                  sA[nb][kq * 4 + 0][o] = ra0.x; sA[nb][kq * 4 + 1][o] = ra0.y;
                  sA[nb][kq * 4 + 2][o] = ra0.z; sA[nb][kq * 4 + 3][o] = ra0.w; }
                { int f = tid + 256; int o = f >> 2, kq = f & 3;
                  sA[nb][kq * 4 + 0][o] = ra1.x; sA[nb][kq * 4 + 1][o] = ra1.y;
                  sA[nb][kq * 4 + 2][o] = ra1.z; sA[nb][kq * 4 + 3][o] = ra1.w; }
            }
            { int f = tid;       int kk = f >> 5, p4 = f & 31; *(float4*)&sB[nb][kk][p4 * 4] = rb0; }
            { int f = tid + 256; int kk = f >> 5, p4 = f & 31; *(float4*)&sB[nb][kk][p4 * 4] = rb1; }
            __syncthreads();
            cur = nb;
        }
    }

    // epilogue
    float cs[8];
    if (cscale) {
        #pragma unroll
        for (int j = 0; j < 8; j++)
            cs[j] = cscale[(size_t)b * strideCS + p0 + tx * 8 + j];
    }
    #pragma unroll
    for (int i = 0; i < 8; i++) {
        int o = o0 + ty * 8 + i;
        float bv = bias ? bias[o] : 0.f;
        float g = 0.f, bt = 0.f;
        if (film) { g = film[(size_t)b * 512 + o]; bt = film[(size_t)b * 512 + 256 + o]; }
        float vo[8];
        #pragma unroll
        for (int jp = 0; jp < 4; jp++) {
            float lo, hi;
            asm("mov.b64 {%0, %1}, %2;" : "=f"(lo), "=f"(hi) : "l"(acc[i][jp]));
            vo[2 * jp] = lo; vo[2 * jp + 1] = hi;
        }
        size_t yrow = (size_t)o * 4096 + p0 + tx * 8;
        #pragma unroll
        for (int j = 0; j < 8; j++) {
            float v = vo[j] * alpha + bv;
            if (film) v = (1.f + g) * v + bt;
            if (cscale) v *= cs[j];
            if (res) v += res[(size_t)b * strideRes + yrow + j];
            vo[j] = v;
        }
        *(float4*)&Yb[yrow]     = make_float4(vo[0], vo[1], vo[2], vo[3]);
        *(float4*)&Yb[yrow + 4] = make_float4(vo[4], vo[5], vo[6], vo[7]);
    }
}

// ---------------- column softmax over St[t][s] (softmax over t per column s) ----------------
// grid (32, B), block 128
__global__ void smax_max_kernel(const float* __restrict__ S, float* __restrict__ rdx) {
    int s = blockIdx.x * 128 + threadIdx.x;
    int b = blockIdx.y;
    const float* Sb = S + (size_t)b * HWSZ * HWSZ;
    float m0 = -1e30f, m1 = -1e30f, m2 = -1e30f, m3 = -1e30f;
    #pragma unroll 2
    for (int t = 0; t < HWSZ; t += 4) {
        m0 = fmaxf(m0, Sb[(size_t)(t + 0) * 4096 + s]);
        m1 = fmaxf(m1, Sb[(size_t)(t + 1) * 4096 + s]);
        m2 = fmaxf(m2, Sb[(size_t)(t + 2) * 4096 + s]);
        m3 = fmaxf(m3, Sb[(size_t)(t + 3) * 4096 + s]);
    }
    rdx[b * 8192 + s] = fmaxf(fmaxf(m0, m1), fmaxf(m2, m3));
}

__global__ void smax_exp_kernel(float* __restrict__ S, float* __restrict__ rdx) {
    int s = blockIdx.x * 128 + threadIdx.x;
    int b = blockIdx.y;
    float* Sb = S + (size_t)b * HWSZ * HWSZ;
    float mx = rdx[b * 8192 + s];
    float s0 = 0.f, s1 = 0.f, s2 = 0.f, s3 = 0.f;
    #pragma unroll 2
    for (int t = 0; t < HWSZ; t += 4) {
        size_t i0 = (size_t)(t + 0) * 4096 + s;
        size_t i1 = (size_t)(t + 1) * 4096 + s;
        size_t i2 = (size_t)(t + 2) * 4096 + s;
        size_t i3 = (size_t)(t + 3) * 4096 + s;
        float e0 = __expf(Sb[i0] - mx); Sb[i0] = e0; s0 += e0;
        float e1 = __expf(Sb[i1] - mx); Sb[i1] = e1; s1 += e1;
        float e2 = __expf(Sb[i2] - mx); Sb[i2] = e2; s2 += e2;
        float e3 = __expf(Sb[i3] - mx); Sb[i3] = e3; s3 += e3;
    }
    rdx[b * 8192 + 4096 + s] = 1.f / ((s0 + s1) + (s2 + s3));
}

// ---------------- host launch ----------------
extern "C" void kernel_launch(void* const* d_in, const int* in_sizes, int n_in,
                              void* d_out, int out_size) {
    const float* x       = (const float*)d_in[0];
    const float* te      = (const float*)d_in[1];
    const float* gn1_s   = (const float*)d_in[2];
    const float* gn1_b   = (const float*)d_in[3];
    const float* conv1_w = (const float*)d_in[4];
    const float* conv1_b = (const float*)d_in[5];
    const float* mlp_w   = (const float*)d_in[6];
    const float* mlp_b   = (const float*)d_in[7];
    const float* gn2_s   = (const float*)d_in[8];
    const float* gn2_b   = (const float*)d_in[9];
    const float* conv2_w = (const float*)d_in[10];
    const float* conv2_b = (const float*)d_in[11];
    const float* gnA_s   = (const float*)d_in[12];
    const float* gnA_b   = (const float*)d_in[13];
    const float* qkv_w   = (const float*)d_in[14];
    const float* out_w   = (const float*)d_in[15];
    const float* out_b   = (const float*)d_in[16];
    float* out = (float*)d_out;

    float *a, *h, *xr, *qkv, *ao, *gb, *col, *S, *rdx;
    cudaGetSymbolAddress((void**)&a,   g_a);
    cudaGetSymbolAddress((void**)&h,   g_h);
    cudaGetSymbolAddress((void**)&xr,  g_xr);
    cudaGetSymbolAddress((void**)&qkv, g_qkv);
    cudaGetSymbolAddress((void**)&ao,  g_ao);
    cudaGetSymbolAddress((void**)&gb,  g_gb);
    cudaGetSymbolAddress((void**)&col, g_col);
    cudaGetSymbolAddress((void**)&S,   g_S);
    cudaGetSymbolAddress((void**)&rdx, g_rdx);

    const long long CHW = 1LL << 20;       // C*HW
    const long long COLS = 2304LL * 4096;  // im2col per-batch
    const long long SST = 1LL << 24;       // HW*HW

    // FiLM gamma/beta (independent; launch early)
    film_mlp_kernel<<<dim3(BB, 4), 128>>>(te, mlp_w, mlp_b, gb);

    // ---- conv1: gn1+silu -> im2col -> GEMM (+bias, +FiLM) ----
    gn_kernel<<<BB * 32, 256>>>(x, gn1_s, gn1_b, a, 1);
    im2col_kernel<<<dim3(4, 2304, BB), 256>>>(a, col);
    gemm128_kernel<<<dim3(32, 2, BB), 256>>>(
        conv1_w, col, h, 2304, 0, 2304, 0LL, COLS, CHW,
        conv1_b, gb, (const float*)0, 0LL, (const float*)0, 0LL, 1.f);

    // ---- conv2: gn2+silu -> im2col -> GEMM (+bias, +x residual) -> xr ----
    gn_kernel<<<BB * 32, 256>>>(h, gn2_s, gn2_b, a, 1);
    im2col_kernel<<<dim3(4, 2304, BB), 256>>>(a, col);
    gemm128_kernel<<<dim3(32, 2, BB), 256>>>(
        conv2_w, col, xr, 2304, 0, 2304, 0LL, COLS, CHW,
        conv2_b, (const float*)0, x, CHW, (const float*)0, 0LL, 1.f);

    // ---- attention ----
    gn_kernel<<<BB * 32, 256>>>(xr, gnA_s, gnA_b, a, 0);
    // qkv = qkv_w @ a
    gemm128_kernel<<<dim3(32, 6, BB), 256>>>(
        qkv_w, a, qkv, 256, 0, 256, 0LL, CHW, 3 * CHW,
        (const float*)0, (const float*)0, (const float*)0, 0LL, (const float*)0, 0LL, 1.f);
    // St[t][s] = sum_c K[c][t] * Q[c][s] / 16
    gemm128_kernel<<<dim3(32, 32, BB), 256>>>(
        qkv + CHW, qkv, S, 256, 1, 4096, 3 * CHW, 3 * CHW, SST,
        (const float*)0, (const float*)0, (const float*)0, 0LL, (const float*)0, 0LL, 0.0625f);
    // column softmax over t
    smax_max_kernel<<<dim3(32, BB), 128>>>(S, rdx);
    smax_exp_kernel<<<dim3(32, BB), 128>>>(S, rdx);
    // ao[d][s] = sum_t V[d][t] * P[t][s] * invsum[s]
    gemm128_kernel<<<dim3(32, 2, BB), 256>>>(
        qkv + 2 * CHW, S, ao, 4096, 0, 4096, 3 * CHW, SST, CHW,
        (const float*)0, (const float*)0, (const float*)0, 0LL, rdx + 4096, 8192LL, 1.f);
    // out = out_w @ ao + out_b + xr
    gemm128_kernel<<<dim3(32, 2, BB), 256>>>(
        out_w, ao, out, 256, 0, 256, 0LL, CHW, CHW,
        out_b, (const float*)0, xr, CHW, (const float*)0, 0LL, 1.f);
}

// round 5
// speedup vs baseline: 2.6964x; 2.6964x over previous
#include <cuda_runtime.h>
#include <math.h>

#define BB 4
#define CHW 1048576LL
#define SST 16777216LL
#define KC 2304

__device__ float g_xh [BB*CHW];
__device__ float g_a  [BB*CHW];
__device__ float g_h  [BB*CHW];
__device__ float g_xr [BB*CHW];
__device__ float g_qkv[BB*3*CHW];
__device__ float g_vt [BB*CHW];
__device__ float g_ao [BB*CHW];
__device__ float g_tmp[BB*CHW];
__device__ float g_col[BB*KC*4096LL];
__device__ float g_S  [BB*SST];
__device__ float g_gb [BB*512];
__device__ float g_rs [BB*4096];
__device__ float g_w1t[256*KC];
__device__ float g_w2t[256*KC];

__device__ __forceinline__ unsigned smem_u32(const void* p){
    unsigned r;
    asm("{ .reg .u64 t; cvta.to.shared.u64 t, %1; cvt.u32.u64 %0, t; }" : "=r"(r) : "l"(p));
    return r;
}
__device__ __forceinline__ unsigned cvt_tf32(float f){
    unsigned r; asm("cvt.rna.tf32.f32 %0, %1;" : "=r"(r) : "f"(f)); return r;
}
__device__ __forceinline__ unsigned swz(unsigned off){ return off ^ ((off >> 3) & 0x70u); }

#define LDMX4(r, addr) \
    asm volatile("ldmatrix.sync.aligned.m8n8.x4.shared.b16 {%0,%1,%2,%3}, [%4];" \
        : "=r"((r)[0]),"=r"((r)[1]),"=r"((r)[2]),"=r"((r)[3]) : "r"(addr))

#define MMA(c, a, b0, b1) \
    asm volatile("mma.sync.aligned.m16n8k8.row.col.f32.tf32.tf32.f32 " \
        "{%0,%1,%2,%3},{%4,%5,%6,%7},{%8,%9},{%0,%1,%2,%3};" \
        : "+f"((c)[0]),"+f"((c)[1]),"+f"((c)[2]),"+f"((c)[3]) \
        : "r"((a)[0]),"r"((a)[1]),"r"((a)[2]),"r"((a)[3]),"r"(b0),"r"(b1))

// D[b][m][n] = alpha * sum_k A[b][m][k]*B[b][n][k]; +bias[n]; FiLM(n); *rscale[m]; +res
// grid (M/128, N/128, BB), block 256. smem 64KB dynamic.
__global__ void __launch_bounds__(256) gemm_mma(
    const float* __restrict__ A, int lda, long long sA,
    const float* __restrict__ B, int ldb, long long sB,
    float* __restrict__ Y, int ldy, long long sY,
    int K, float alpha,
    const float* __restrict__ bias, const float* __restrict__ film,
    const float* __restrict__ rscale,
    const float* __restrict__ res, int ldr, long long sR)
{
    extern __shared__ char smem[];   // A: [2][16384], B at 32768: [2][16384]
    unsigned sbase = smem_u32(smem);
    int tid = threadIdx.x, lane = tid & 31, wid = tid >> 5;
    int warp_m = wid & 3, warp_n = wid >> 2;
    int b = blockIdx.z;
    int m0 = blockIdx.x * 128, n0 = blockIdx.y * 128;
    const float* Ab = A + sA * b + (size_t)m0 * lda;
    const float* Bb = B + sB * b + (size_t)n0 * ldb;

    int lrow = tid >> 1;            // 0..127
    int koff = (tid & 1) * 16;      // floats

    float acc[2][8][4];
    #pragma unroll
    for (int mi = 0; mi < 2; mi++)
        #pragma unroll
        for (int ni = 0; ni < 8; ni++)
            #pragma unroll
            for (int e = 0; e < 4; e++) acc[mi][ni][e] = 0.f;

    float4 pa[4], pb[4];
#define LOAD_REGS(kb) { \
        const float* Ap = Ab + (size_t)lrow * lda + (kb) * 32 + koff; \
        const float* Bp = Bb + (size_t)lrow * ldb + (kb) * 32 + koff; \
        pa[0] = *(const float4*)(Ap);      pa[1] = *(const float4*)(Ap + 4); \
        pa[2] = *(const float4*)(Ap + 8);  pa[3] = *(const float4*)(Ap + 12); \
        pb[0] = *(const float4*)(Bp);      pb[1] = *(const float4*)(Bp + 4); \
        pb[2] = *(const float4*)(Bp + 8);  pb[3] = *(const float4*)(Bp + 12); }
#define STORE_STAGE(st) { \
        char* sa  = smem + (st) * 16384; \
        char* sbm = smem + 32768 + (st) * 16384; \
        unsigned ob = (unsigned)lrow * 128u + (unsigned)koff * 4u; \
        _Pragma("unroll") \
        for (int j = 0; j < 4; j++) { \
            uint4 va = { cvt_tf32(pa[j].x), cvt_tf32(pa[j].y), cvt_tf32(pa[j].z), cvt_tf32(pa[j].w) }; \
            uint4 vb = { cvt_tf32(pb[j].x), cvt_tf32(pb[j].y), cvt_tf32(pb[j].z), cvt_tf32(pb[j].w) }; \
            *(uint4*)(sa  + swz(ob + j * 16)) = va; \
            *(uint4*)(sbm + swz(ob + j * 16)) = vb; } }

    LOAD_REGS(0);
    STORE_STAGE(0);
    __syncthreads();

    int nkb = K >> 5, cur = 0;
    unsigned arow_base = (unsigned)(warp_m * 32 + (lane & 7) + (lane & 8));
    unsigned acol = (lane & 16) ? 16u : 0u;
    unsigned brow_base = (unsigned)(warp_n * 64 + (lane & 7) + ((lane & 16) >> 1));
    unsigned bcol = (lane & 8) ? 16u : 0u;

    for (int kb = 0; kb < nkb; kb++) {
        if (kb + 1 < nkb) LOAD_REGS(kb + 1);
        unsigned saB = sbase + cur * 16384u;
        unsigned sbB = sbase + 32768u + cur * 16384u;
        #pragma unroll
        for (int k8 = 0; k8 < 4; k8++) {
            unsigned kc4 = k8 * 32u;
            unsigned af[2][4], bf[4][4];
            #pragma unroll
            for (int mi = 0; mi < 2; mi++) {
                unsigned off = (arow_base + mi * 16u) * 128u + kc4 + acol;
                LDMX4(af[mi], saB + swz(off));
            }
            #pragma unroll
            for (int pi = 0; pi < 4; pi++) {
                unsigned off = (brow_base + pi * 16u) * 128u + kc4 + bcol;
                LDMX4(bf[pi], sbB + swz(off));
            }
            #pragma unroll
            for (int mi = 0; mi < 2; mi++)
                #pragma unroll
                for (int pi = 0; pi < 4; pi++) {
                    MMA(acc[mi][2*pi],   af[mi], bf[pi][0], bf[pi][1]);
                    MMA(acc[mi][2*pi+1], af[mi], bf[pi][2], bf[pi][3]);
                }
        }
        if (kb + 1 < nkb) {
            STORE_STAGE(cur ^ 1);
            __syncthreads();
            cur ^= 1;
        }
    }

    // epilogue: d0,d1 = (row g, cols 2t,2t+1); d2,d3 = (row g+8)
    int g = lane >> 2, t = lane & 3;
    #pragma unroll
    for (int mi = 0; mi < 2; mi++) {
        #pragma unroll
        for (int r = 0; r < 2; r++) {
            int m = m0 + warp_m * 32 + mi * 16 + g + r * 8;
            float rsv = rscale ? rscale[(size_t)b * 4096 + m] : 1.f;
            float* Yr = Y + sY * b + (size_t)m * ldy;
            const float* Rr = res ? (res + sR * b + (size_t)m * ldr) : (const float*)0;
            #pragma unroll
            for (int ni = 0; ni < 8; ni++) {
                int n = n0 + warp_n * 64 + ni * 8 + 2 * t;
                float v0 = acc[mi][ni][2*r]     * alpha;
                float v1 = acc[mi][ni][2*r + 1] * alpha;
                if (bias) { v0 += bias[n]; v1 += bias[n + 1]; }
                if (film) {
                    const float* fg = film + (size_t)b * 512 + n;
                    v0 = (1.f + fg[0]) * v0 + fg[256];
                    v1 = (1.f + fg[1]) * v1 + fg[257];
                }
                v0 *= rsv; v1 *= rsv;
                if (Rr) { v0 += Rr[n]; v1 += Rr[n + 1]; }
                *(float2*)&Yr[n] = make_float2(v0, v1);
            }
        }
    }
}

// out[b][j][i] = in[b][i][j]; grid (I/32, J/32, BB), block (32,8)
__global__ void tr_kernel(const float* __restrict__ in, float* __restrict__ out,
                          int ldin, int ldout, long long sIn, long long sOut) {
    __shared__ float t[32][33];
    int i0 = blockIdx.x * 32, j0 = blockIdx.y * 32, b = blockIdx.z;
    int tx = threadIdx.x, ty = threadIdx.y;
    #pragma unroll
    for (int r = 0; r < 4; r++)
        t[ty + r*8][tx] = in[sIn*b + (size_t)(i0 + ty + r*8) * ldin + j0 + tx];
    __syncthreads();
    #pragma unroll
    for (int r = 0; r < 4; r++)
        out[sOut*b + (size_t)(j0 + ty + r*8) * ldout + i0 + tx] = t[tx][ty + r*8];
}

// GroupNorm NHWC; grid BB*32, block 256
__global__ void gn_nhwc(const float* __restrict__ x, const float* __restrict__ sc,
                        const float* __restrict__ bi, float* __restrict__ y, int dosilu) {
    __shared__ float rsh[256], rqh[256], mv[2];
    int b = blockIdx.x >> 5, g = blockIdx.x & 31;
    const float* xp = x + (size_t)b * CHW + g * 8;
    float* yp = y + (size_t)b * CHW + g * 8;
    int tid = threadIdx.x;
    float sum = 0.f, sq = 0.f;
    for (int i = tid; i < 4096; i += 256) {
        float4 v0 = *(const float4*)&xp[(size_t)i * 256];
        float4 v1 = *(const float4*)&xp[(size_t)i * 256 + 4];
        sum += (v0.x+v0.y)+(v0.z+v0.w)+(v1.x+v1.y)+(v1.z+v1.w);
        sq += v0.x*v0.x+v0.y*v0.y+v0.z*v0.z+v0.w*v0.w+v1.x*v1.x+v1.y*v1.y+v1.z*v1.z+v1.w*v1.w;
    }
    rsh[tid] = sum; rqh[tid] = sq;
    __syncthreads();
    for (int st = 128; st > 0; st >>= 1) {
        if (tid < st) { rsh[tid] += rsh[tid+st]; rqh[tid] += rqh[tid+st]; }
        __syncthreads();
    }
    if (tid == 0) {
        float m = rsh[0] * (1.f/32768.f);
        mv[0] = m; mv[1] = rsqrtf(rqh[0] * (1.f/32768.f) - m*m + 1e-5f);
    }
    __syncthreads();
    float m = mv[0], inv = mv[1], aa[8], bb[8];
    #pragma unroll
    for (int j = 0; j < 8; j++) { aa[j] = inv * sc[g*8+j]; bb[j] = bi[g*8+j] - m * aa[j]; }
    for (int i = tid; i < 4096; i += 256) {
        float4 v0 = *(const float4*)&xp[(size_t)i * 256];
        float4 v1 = *(const float4*)&xp[(size_t)i * 256 + 4];
        float v[8] = { v0.x,v0.y,v0.z,v0.w,v1.x,v1.y,v1.z,v1.w };
        #pragma unroll
        for (int j = 0; j < 8; j++) {
            float tv = v[j]*aa[j] + bb[j];
            if (dosilu) tv = tv / (1.f + __expf(-tv));
            v[j] = tv;
        }
        *(float4*)&yp[(size_t)i*256]   = make_float4(v[0],v[1],v[2],v[3]);
        *(float4*)&yp[(size_t)i*256+4] = make_float4(v[4],v[5],v[6],v[7]);
    }
}

// col[b][p][t*256+c]; grid (1024, 9, BB), block 256
__global__ void im2col_nhwc(const float* __restrict__ xh, float* __restrict__ col) {
    int t = blockIdx.y, b = blockIdx.z;
    int kh = t / 3 - 1, kw = t - (t/3)*3 - 1;
    int p = blockIdx.x * 4 + (threadIdx.x >> 6);
    int c4 = (threadIdx.x & 63) * 4;
    int h2 = (p >> 6) + kh, w2 = (p & 63) + kw;
    float4 v = make_float4(0.f, 0.f, 0.f, 0.f);
    if ((unsigned)h2 < 64u && (unsigned)w2 < 64u)
        v = *(const float4*)&xh[(size_t)b * CHW + (size_t)(h2*64 + w2) * 256 + c4];
    *(float4*)&col[((size_t)b * 4096 + p) * KC + t * 256 + c4] = v;
}

// wt[o][t*256+ic] = w[o][ic*9+t]; grid (9, 256), block 256
__global__ void wtrans(const float* __restrict__ w, float* __restrict__ wt) {
    int o = blockIdx.y;
    int ko = blockIdx.x * 256 + threadIdx.x;
    wt[(size_t)o * KC + ko] = w[(size_t)o * KC + (ko & 255) * 9 + (ko >> 8)];
}

// grid (BB, 4), block 128
__global__ void film_mlp(const float* __restrict__ te, const float* __restrict__ w,
                         const float* __restrict__ bi, float* __restrict__ gb) {
    __shared__ float s_te[256];
    int b = blockIdx.x, tid = threadIdx.x;
    for (int i = tid; i < 256; i += 128) {
        float v = te[b * 256 + i];
        s_te[i] = v / (1.f + __expf(-v));
    }
    __syncthreads();
    int j = blockIdx.y * 128 + tid;
    const float* wr = w + (size_t)j * 256;
    float acc = bi[j];
    for (int t = 0; t < 256; t++) acc += s_te[t] * wr[t];
    gb[b * 512 + j] = acc;
}

// row softmax, 1/sum -> rs; grid (4096, BB), block 128
__global__ void softmax_row(float* __restrict__ S, float* __restrict__ rs) {
    __shared__ float red[4];
    float* p = S + (size_t)blockIdx.y * SST + (size_t)blockIdx.x * 4096;
    int tid = threadIdx.x, lane = tid & 31, wid = tid >> 5;
    float4 v[8];
    float mx = -1e30f;
    #pragma unroll
    for (int k = 0; k < 8; k++) {
        v[k] = ((const float4*)p)[tid + k*128];
        mx = fmaxf(mx, fmaxf(fmaxf(v[k].x, v[k].y), fmaxf(v[k].z, v[k].w)));
    }
    #pragma unroll
    for (int o = 16; o; o >>= 1) mx = fmaxf(mx, __shfl_xor_sync(~0u, mx, o));
    if (lane == 0) red[wid] = mx;
    __syncthreads();
    mx = fmaxf(fmaxf(red[0], red[1]), fmaxf(red[2], red[3]));
    __syncthreads();
    float sm = 0.f;
    #pragma unroll
    for (int k = 0; k < 8; k++) {
        v[k].x = __expf(v[k].x - mx); v[k].y = __expf(v[k].y - mx);
        v[k].z = __expf(v[k].z - mx); v[k].w = __expf(v[k].w - mx);
        sm += (v[k].x + v[k].y) + (v[k].z + v[k].w);
        ((float4*)p)[tid + k*128] = v[k];
    }
    #pragma unroll
    for (int o = 16; o; o >>= 1) sm += __shfl_xor_sync(~0u, sm, o);
    if (lane == 0) red[wid] = sm;
    __syncthreads();
    if (tid == 0)
        rs[(size_t)blockIdx.y * 4096 + blockIdx.x] = 1.f / (red[0]+red[1]+red[2]+red[3]);
}

extern "C" void kernel_launch(void* const* d_in, const int* in_sizes, int n_in,
                              void* d_out, int out_size) {
    const float* x = (const float*)d_in[0];
    const float* te = (const float*)d_in[1];
    const float* gn1_s = (const float*)d_in[2];
    const float* gn1_b = (const float*)d_in[3];
    const float* conv1_w = (const float*)d_in[4];
    const float* conv1_b = (const float*)d_in[5];
    const float* mlp_w = (const float*)d_in[6];
    const float* mlp_b = (const float*)d_in[7];
    const float* gn2_s = (const float*)d_in[8];
    const float* gn2_b = (const float*)d_in[9];
    const float* conv2_w = (const float*)d_in[10];
    const float* conv2_b = (const float*)d_in[11];
    const float* gnA_s = (const float*)d_in[12];
    const float* gnA_b = (const float*)d_in[13];
    const float* qkv_w = (const float*)d_in[14];
    const float* out_w = (const float*)d_in[15];
    const float* out_b = (const float*)d_in[16];
    float* out = (float*)d_out;

    float *xh,*a,*h,*xr,*qkv,*vt,*ao,*tmp,*col,*S,*gb,*rs,*w1t,*w2t;
    cudaGetSymbolAddress((void**)&xh, g_xh);  cudaGetSymbolAddress((void**)&a, g_a);
    cudaGetSymbolAddress((void**)&h, g_h);    cudaGetSymbolAddress((void**)&xr, g_xr);
    cudaGetSymbolAddress((void**)&qkv, g_qkv);cudaGetSymbolAddress((void**)&vt, g_vt);
    cudaGetSymbolAddress((void**)&ao, g_ao);  cudaGetSymbolAddress((void**)&tmp, g_tmp);
    cudaGetSymbolAddress((void**)&col, g_col);cudaGetSymbolAddress((void**)&S, g_S);
    cudaGetSymbolAddress((void**)&gb, g_gb);  cudaGetSymbolAddress((void**)&rs, g_rs);
    cudaGetSymbolAddress((void**)&w1t, g_w1t);cudaGetSymbolAddress((void**)&w2t, g_w2t);

    static int init_done = 0;
    if (!init_done) {
        cudaFuncSetAttribute(gemm_mma, cudaFuncAttributeMaxDynamicSharedMemorySize, 65536);
        init_done = 1;
    }
    const float* NUL = (const float*)0;
    dim3 tb(32, 8);

    film_mlp<<<dim3(BB, 4), 128>>>(te, mlp_w, mlp_b, gb);
    wtrans<<<dim3(9, 256), 256>>>(conv1_w, w1t);
    wtrans<<<dim3(9, 256), 256>>>(conv2_w, w2t);
    tr_kernel<<<dim3(8, 128, BB), tb>>>(x, xh, 4096, 256, CHW, CHW);   // NCHW->NHWC

    gn_nhwc<<<BB*32, 256>>>(xh, gn1_s, gn1_b, a, 1);
    im2col_nhwc<<<dim3(1024, 9, BB), 256>>>(a, col);
    gemm_mma<<<dim3(32, 2, BB), 256, 65536>>>(col, KC, KC*4096LL, w1t, KC, 0LL,
        h, 256, CHW, KC, 1.f, conv1_b, gb, NUL, NUL, 0, 0LL);

    gn_nhwc<<<BB*32, 256>>>(h, gn2_s, gn2_b, a, 1);
    im2col_nhwc<<<dim3(1024, 9, BB), 256>>>(a, col);
    gemm_mma<<<dim3(32, 2, BB), 256, 65536>>>(col, KC, KC*4096LL, w2t, KC, 0LL,
        xr, 256, CHW, KC, 1.f, conv2_b, NUL, NUL, xh, 256, CHW);

    gn_nhwc<<<BB*32, 256>>>(xr, gnA_s, gnA_b, a, 0);
    gemm_mma<<<dim3(32, 6, BB), 256, 65536>>>(a, 256, CHW, qkv_w, 256, 0LL,
        qkv, 768, 3*CHW, 256, 1.f, NUL, NUL, NUL, NUL, 0, 0LL);
    gemm_mma<<<dim3(32, 32, BB), 256, 65536>>>(qkv, 768, 3*CHW, qkv + 256, 768, 3*CHW,
        S, 4096, SST, 256, 0.0625f, NUL, NUL, NUL, NUL, 0, 0LL);
    softmax_row<<<dim3(4096, BB), 128>>>(S, rs);
    tr_kernel<<<dim3(128, 8, BB), tb>>>(qkv + 512, vt, 768, 4096, 3*CHW, CHW);  // V -> [d][t]
    gemm_mma<<<dim3(32, 2, BB), 256, 65536>>>(S, 4096, SST, vt, 4096, CHW,
        ao, 256, CHW, 4096, 1.f, NUL, NUL, rs, NUL, 0, 0LL);
    gemm_mma<<<dim3(32, 2, BB), 256, 65536>>>(ao, 256, CHW, out_w, 256, 0LL,
        tmp, 256, CHW, 256, 1.f, out_b, NUL, NUL, xr, 256, CHW);
    tr_kernel<<<dim3(128, 8, BB), tb>>>(tmp, out, 256, 4096, CHW, CHW);  // NHWC->NCHW
}

// round 6
// speedup vs baseline: 3.6053x; 1.3371x over previous
#include <cuda_runtime.h>
#include <math.h>

#define BB 4
#define CHW 1048576LL
#define SST 16777216LL
#define KC 2304

__device__ float g_xh [BB*CHW];
__device__ float g_a  [BB*CHW];
__device__ float g_h  [BB*CHW];
__device__ float g_xr [BB*CHW];
__device__ float g_qkv[BB*3*CHW];
__device__ float g_vt [BB*CHW];
__device__ float g_ao [BB*CHW];
__device__ float g_tmp[BB*CHW];
__device__ float g_col[BB*KC*4096LL];
__device__ float g_S  [BB*SST];
__device__ float g_gb [BB*512];
__device__ float g_rs [BB*4096];
__device__ float g_w1t[256*KC];
__device__ float g_w2t[256*KC];
__device__ float g_qkvw[768*256];
__device__ float g_outw[256*256];

__device__ __forceinline__ unsigned smem_u32(const void* p){
    unsigned r;
    asm("{ .reg .u64 t; cvta.to.shared.u64 t, %1; cvt.u32.u64 %0, t; }" : "=r"(r) : "l"(p));
    return r;
}
__device__ __forceinline__ float rnd_tf32(float f){
    unsigned r; asm("cvt.rna.tf32.f32 %0, %1;" : "=r"(r) : "f"(f));
    return __uint_as_float(r);
}
__device__ __forceinline__ unsigned swz(unsigned off){ return off ^ ((off >> 3) & 0x70u); }

#define LDMX4(r, addr) \
    asm volatile("ldmatrix.sync.aligned.m8n8.x4.shared.b16 {%0,%1,%2,%3}, [%4];" \
        : "=r"((r)[0]),"=r"((r)[1]),"=r"((r)[2]),"=r"((r)[3]) : "r"(addr))
#define MMA(c, a, b0, b1) \
    asm volatile("mma.sync.aligned.m16n8k8.row.col.f32.tf32.tf32.f32 " \
        "{%0,%1,%2,%3},{%4,%5,%6,%7},{%8,%9},{%0,%1,%2,%3};" \
        : "+f"((c)[0]),"+f"((c)[1]),"+f"((c)[2]),"+f"((c)[3]) \
        : "r"((a)[0]),"r"((a)[1]),"r"((a)[2]),"r"((a)[3]),"r"(b0),"r"(b1))

// D[b][m][n] = alpha*sum_k A[b][m][k]*B[b][n][k]; +bias; FiLM; *rscale[m]; +res; opt tf32-round
// Inputs must be tf32-pre-rounded. grid (M/256, N/128, BB), block 256, smem 147456.
__global__ void __launch_bounds__(256, 1) gemm_cp(
    const float* __restrict__ A, int lda, long long sA,
    const float* __restrict__ B, int ldb, long long sB,
    float* __restrict__ Y, int ldy, long long sY,
    int K, float alpha,
    const float* __restrict__ bias, const float* __restrict__ film,
    const float* __restrict__ rscale,
    const float* __restrict__ res, int ldr, long long sR, int roundOut)
{
    extern __shared__ char smem[];
    unsigned sbase = smem_u32(smem);
    int tid = threadIdx.x, lane = tid & 31, wid = tid >> 5;
    int warp_m = wid & 3, warp_n = wid >> 2;  // 4m x 2n, warp tile 64x64
    int b = blockIdx.z;
    int m0 = blockIdx.x * 256, n0 = blockIdx.y * 128;
    const float* Ab = A + sA * b + (size_t)m0 * lda;
    const float* Bb = B + sB * b + (size_t)n0 * ldb;

    float acc[4][8][4];
    #pragma unroll
    for (int mi = 0; mi < 4; mi++)
        #pragma unroll
        for (int ni = 0; ni < 8; ni++)
            #pragma unroll
            for (int e = 0; e < 4; e++) acc[mi][ni][e] = 0.f;

#define ISSUE(st, kb) { \
    unsigned ab_ = sbase + (st) * 32768u; \
    unsigned bb_ = sbase + 98304u + (st) * 16384u; \
    const float* As_ = Ab + (kb) * 32; \
    const float* Bs_ = Bb + (kb) * 32; \
    _Pragma("unroll") \
    for (int i_ = 0; i_ < 8; i_++) { \
        int c_ = tid + i_ * 256; int row_ = c_ >> 3, seg_ = c_ & 7; \
        unsigned d_ = ab_ + swz((unsigned)row_ * 128u + seg_ * 16u); \
        asm volatile("cp.async.cg.shared.global [%0], [%1], 16;" :: "r"(d_), "l"(As_ + (size_t)row_ * lda + seg_ * 4)); } \
    _Pragma("unroll") \
    for (int i_ = 0; i_ < 4; i_++) { \
        int c_ = tid + i_ * 256; int row_ = c_ >> 3, seg_ = c_ & 7; \
        unsigned d_ = bb_ + swz((unsigned)row_ * 128u + seg_ * 16u); \
        asm volatile("cp.async.cg.shared.global [%0], [%1], 16;" :: "r"(d_), "l"(Bs_ + (size_t)row_ * ldb + seg_ * 4)); } \
    asm volatile("cp.async.commit_group;"); }

    int nkb = K >> 5;
    ISSUE(0, 0);
    ISSUE(1, 1);

    unsigned arow = (unsigned)(warp_m * 64 + (lane & 7) + (lane & 8));
    unsigned acol = (lane & 16) ? 16u : 0u;
    unsigned brow = (unsigned)(warp_n * 64 + (lane & 7) + ((lane & 16) >> 1));
    unsigned bcol = (lane & 8) ? 16u : 0u;

    for (int kb = 0; kb < nkb; kb++) {
        int st = kb % 3;
        asm volatile("cp.async.wait_group 1;" ::: "memory");
        __syncthreads();
        unsigned ab_ = sbase + st * 32768u;
        unsigned bb_ = sbase + 98304u + st * 16384u;
        #pragma unroll
        for (int k8 = 0; k8 < 4; k8++) {
            unsigned kc = k8 * 32u;
            unsigned af[4][4], bf[4][4];
            #pragma unroll
            for (int mi = 0; mi < 4; mi++)
                LDMX4(af[mi], ab_ + swz((arow + mi * 16u) * 128u + kc + acol));
            #pragma unroll
            for (int pi = 0; pi < 4; pi++)
                LDMX4(bf[pi], bb_ + swz((brow + pi * 16u) * 128u + kc + bcol));
            #pragma unroll
            for (int mi = 0; mi < 4; mi++)
                #pragma unroll
                for (int pi = 0; pi < 4; pi++) {
                    MMA(acc[mi][2*pi],   af[mi], bf[pi][0], bf[pi][1]);
                    MMA(acc[mi][2*pi+1], af[mi], bf[pi][2], bf[pi][3]);
                }
        }
        if (kb + 2 < nkb) { ISSUE((kb + 2) % 3, kb + 2); }
        else asm volatile("cp.async.commit_group;");
    }

    int g = lane >> 2, t = lane & 3;
    #pragma unroll
    for (int mi = 0; mi < 4; mi++) {
        #pragma unroll
        for (int r = 0; r < 2; r++) {
            int m = m0 + warp_m * 64 + mi * 16 + g + r * 8;
            float rsv = rscale ? rscale[(size_t)b * 4096 + m] : 1.f;
            float* Yr = Y + sY * b + (size_t)m * ldy;
            const float* Rr = res ? (res + sR * b + (size_t)m * ldr) : (const float*)0;
            #pragma unroll
            for (int ni = 0; ni < 8; ni++) {
                int n = n0 + warp_n * 64 + ni * 8 + 2 * t;
                float v0 = acc[mi][ni][2*r]     * alpha;
                float v1 = acc[mi][ni][2*r + 1] * alpha;
                if (bias) { v0 += bias[n]; v1 += bias[n + 1]; }
                if (film) {
                    const float* fg = film + (size_t)b * 512 + n;
                    v0 = (1.f + fg[0]) * v0 + fg[256];
                    v1 = (1.f + fg[1]) * v1 + fg[257];
                }
                v0 *= rsv; v1 *= rsv;
                if (Rr) { v0 += Rr[n]; v1 += Rr[n + 1]; }
                if (roundOut) { v0 = rnd_tf32(v0); v1 = rnd_tf32(v1); }
                *(float2*)&Yr[n] = make_float2(v0, v1);
            }
        }
    }
}

// out[b][j][i] = in[b][i][j]; grid (I/32, J/32, BB), block (32,8)
__global__ void tr_kernel(const float* __restrict__ in, float* __restrict__ out,
                          int ldin, int ldout, long long sIn, long long sOut, int rnd) {
    __shared__ float t[32][33];
    int i0 = blockIdx.x * 32, j0 = blockIdx.y * 32, b = blockIdx.z;
    int tx = threadIdx.x, ty = threadIdx.y;
    #pragma unroll
    for (int r = 0; r < 4; r++)
        t[ty + r*8][tx] = in[sIn*b + (size_t)(i0 + ty + r*8) * ldin + j0 + tx];
    __syncthreads();
    #pragma unroll
    for (int r = 0; r < 4; r++) {
        float v = t[tx][ty + r*8];
        if (rnd) v = rnd_tf32(v);
        out[sOut*b + (size_t)(j0 + ty + r*8) * ldout + i0 + tx] = v;
    }
}

// GroupNorm NHWC (+opt SiLU), tf32-rounded output; grid BB*32, block 256
__global__ void gn_nhwc(const float* __restrict__ x, const float* __restrict__ sc,
                        const float* __restrict__ bi, float* __restrict__ y, int dosilu) {
    __shared__ float rsh[256], rqh[256], mv[2];
    int b = blockIdx.x >> 5, g = blockIdx.x & 31;
    const float* xp = x + (size_t)b * CHW + g * 8;
    float* yp = y + (size_t)b * CHW + g * 8;
    int tid = threadIdx.x;
    float sum = 0.f, sq = 0.f;
    for (int i = tid; i < 4096; i += 256) {
        float4 v0 = *(const float4*)&xp[(size_t)i * 256];
        float4 v1 = *(const float4*)&xp[(size_t)i * 256 + 4];
        sum += (v0.x+v0.y)+(v0.z+v0.w)+(v1.x+v1.y)+(v1.z+v1.w);
        sq += v0.x*v0.x+v0.y*v0.y+v0.z*v0.z+v0.w*v0.w+v1.x*v1.x+v1.y*v1.y+v1.z*v1.z+v1.w*v1.w;
    }
    rsh[tid] = sum; rqh[tid] = sq;
    __syncthreads();
    for (int st = 128; st > 0; st >>= 1) {
        if (tid < st) { rsh[tid] += rsh[tid+st]; rqh[tid] += rqh[tid+st]; }
        __syncthreads();
    }
    if (tid == 0) {
        float m = rsh[0] * (1.f/32768.f);
        mv[0] = m; mv[1] = rsqrtf(rqh[0] * (1.f/32768.f) - m*m + 1e-5f);
    }
    __syncthreads();
    float m = mv[0], inv = mv[1], aa[8], bb[8];
    #pragma unroll
    for (int j = 0; j < 8; j++) { aa[j] = inv * sc[g*8+j]; bb[j] = bi[g*8+j] - m * aa[j]; }
    for (int i = tid; i < 4096; i += 256) {
        float4 v0 = *(const float4*)&xp[(size_t)i * 256];
        float4 v1 = *(const float4*)&xp[(size_t)i * 256 + 4];
        float v[8] = { v0.x,v0.y,v0.z,v0.w,v1.x,v1.y,v1.z,v1.w };
        #pragma unroll
        for (int j = 0; j < 8; j++) {
            float tv = v[j]*aa[j] + bb[j];
            if (dosilu) tv = tv / (1.f + __expf(-tv));
            v[j] = rnd_tf32(tv);
        }
        *(float4*)&yp[(size_t)i*256]   = make_float4(v[0],v[1],v[2],v[3]);
        *(float4*)&yp[(size_t)i*256+4] = make_float4(v[4],v[5],v[6],v[7]);
    }
}

// col[b][p][t*256+c]; grid (1024, 9, BB), block 256 (input already rounded by gn)
__global__ void im2col_nhwc(const float* __restrict__ xh, float* __restrict__ col) {
    int t = blockIdx.y, b = blockIdx.z;
    int kh = t / 3 - 1, kw = t - (t/3)*3 - 1;
    int p = blockIdx.x * 4 + (threadIdx.x >> 6);
    int c4 = (threadIdx.x & 63) * 4;
    int h2 = (p >> 6) + kh, w2 = (p & 63) + kw;
    float4 v = make_float4(0.f, 0.f, 0.f, 0.f);
    if ((unsigned)h2 < 64u && (unsigned)w2 < 64u)
        v = *(const float4*)&xh[(size_t)b * CHW + (size_t)(h2*64 + w2) * 256 + c4];
    *(float4*)&col[((size_t)b * 4096 + p) * KC + t * 256 + c4] = v;
}

// wt[o][t*256+ic] = round(w[o][ic*9+t]); grid (9, 256), block 256
__global__ void wtrans(const float* __restrict__ w, float* __restrict__ wt) {
    int o = blockIdx.y;
    int ko = blockIdx.x * 256 + threadIdx.x;
    wt[(size_t)o * KC + ko] = rnd_tf32(w[(size_t)o * KC + (ko & 255) * 9 + (ko >> 8)]);
}

__global__ void round_copy(const float* __restrict__ in, float* __restrict__ out, int n) {
    int i = blockIdx.x * 256 + threadIdx.x;
    if (i < n) out[i] = rnd_tf32(in[i]);
}

// grid (BB, 4), block 128
__global__ void film_mlp(const float* __restrict__ te, const float* __restrict__ w,
                         const float* __restrict__ bi, float* __restrict__ gb) {
    __shared__ float s_te[256];
    int b = blockIdx.x, tid = threadIdx.x;
    for (int i = tid; i < 256; i += 128) {
        float v = te[b * 256 + i];
        s_te[i] = v / (1.f + __expf(-v));
    }
    __syncthreads();
    int j = blockIdx.y * 128 + tid;
    const float* wr = w + (size_t)j * 256;
    float acc = bi[j];
    for (int t = 0; t < 256; t++) acc += s_te[t] * wr[t];
    gb[b * 512 + j] = acc;
}

// row softmax (stores tf32-rounded P), 1/sum -> rs; grid (4096, BB), block 128
__global__ void softmax_row(float* __restrict__ S, float* __restrict__ rs) {
    __shared__ float red[4];
    float* p = S + (size_t)blockIdx.y * SST + (size_t)blockIdx.x * 4096;
    int tid = threadIdx.x, lane = tid & 31, wid = tid >> 5;
    float4 v[8];
    float mx = -1e30f;
    #pragma unroll
    for (int k = 0; k < 8; k++) {
        v[k] = ((const float4*)p)[tid + k*128];
        mx = fmaxf(mx, fmaxf(fmaxf(v[k].x, v[k].y), fmaxf(v[k].z, v[k].w)));
    }
    #pragma unroll
    for (int o = 16; o; o >>= 1) mx = fmaxf(mx, __shfl_xor_sync(~0u, mx, o));
    if (lane == 0) red[wid] = mx;
    __syncthreads();
    mx = fmaxf(fmaxf(red[0], red[1]), fmaxf(red[2], red[3]));
    __syncthreads();
    float sm = 0.f;
    #pragma unroll
    for (int k = 0; k < 8; k++) {
        v[k].x = __expf(v[k].x - mx); v[k].y = __expf(v[k].y - mx);
        v[k].z = __expf(v[k].z - mx); v[k].w = __expf(v[k].w - mx);
        sm += (v[k].x + v[k].y) + (v[k].z + v[k].w);
        v[k].x = rnd_tf32(v[k].x); v[k].y = rnd_tf32(v[k].y);
        v[k].z = rnd_tf32(v[k].z); v[k].w = rnd_tf32(v[k].w);
        ((float4*)p)[tid + k*128] = v[k];
    }
    #pragma unroll
    for (int o = 16; o; o >>= 1) sm += __shfl_xor_sync(~0u, sm, o);
    if (lane == 0) red[wid] = sm;
    __syncthreads();
    if (tid == 0)
        rs[(size_t)blockIdx.y * 4096 + blockIdx.x] = 1.f / (red[0]+red[1]+red[2]+red[3]);
}

extern "C" void kernel_launch(void* const* d_in, const int* in_sizes, int n_in,
                              void* d_out, int out_size) {
    const float* x = (const float*)d_in[0];
    const float* te = (const float*)d_in[1];
    const float* gn1_s = (const float*)d_in[2];
    const float* gn1_b = (const float*)d_in[3];
    const float* conv1_w = (const float*)d_in[4];
    const float* conv1_b = (const float*)d_in[5];
    const float* mlp_w = (const float*)d_in[6];
    const float* mlp_b = (const float*)d_in[7];
    const float* gn2_s = (const float*)d_in[8];
    const float* gn2_b = (const float*)d_in[9];
    const float* conv2_w = (const float*)d_in[10];
    const float* conv2_b = (const float*)d_in[11];
    const float* gnA_s = (const float*)d_in[12];
    const float* gnA_b = (const float*)d_in[13];
    const float* qkv_w = (const float*)d_in[14];
    const float* out_w = (const float*)d_in[15];
    const float* out_b = (const float*)d_in[16];
    float* out = (float*)d_out;

    float *xh,*a,*h,*xr,*qkv,*vt,*ao,*tmp,*col,*S,*gb,*rs,*w1t,*w2t,*qw,*ow;
    cudaGetSymbolAddress((void**)&xh, g_xh);  cudaGetSymbolAddress((void**)&a, g_a);
    cudaGetSymbolAddress((void**)&h, g_h);    cudaGetSymbolAddress((void**)&xr, g_xr);
    cudaGetSymbolAddress((void**)&qkv, g_qkv);cudaGetSymbolAddress((void**)&vt, g_vt);
    cudaGetSymbolAddress((void**)&ao, g_ao);  cudaGetSymbolAddress((void**)&tmp, g_tmp);
    cudaGetSymbolAddress((void**)&col, g_col);cudaGetSymbolAddress((void**)&S, g_S);
    cudaGetSymbolAddress((void**)&gb, g_gb);  cudaGetSymbolAddress((void**)&rs, g_rs);
    cudaGetSymbolAddress((void**)&w1t, g_w1t);cudaGetSymbolAddress((void**)&w2t, g_w2t);
    cudaGetSymbolAddress((void**)&qw, g_qkvw);cudaGetSymbolAddress((void**)&ow, g_outw);

    static int init_done = 0;
    if (!init_done) {
        cudaFuncSetAttribute(gemm_cp, cudaFuncAttributeMaxDynamicSharedMemorySize, 147456);
        init_done = 1;
    }
    const float* NUL = (const float*)0;
    dim3 tb(32, 8);

    film_mlp<<<dim3(BB, 4), 128>>>(te, mlp_w, mlp_b, gb);
    wtrans<<<dim3(9, 256), 256>>>(conv1_w, w1t);
    wtrans<<<dim3(9, 256), 256>>>(conv2_w, w2t);
    round_copy<<<768, 256>>>(qkv_w, qw, 768 * 256);
    round_copy<<<256, 256>>>(out_w, ow, 256 * 256);
    tr_kernel<<<dim3(8, 128, BB), tb>>>(x, xh, 4096, 256, CHW, CHW, 0);  // NCHW->NHWC

    gn_nhwc<<<BB*32, 256>>>(xh, gn1_s, gn1_b, a, 1);
    im2col_nhwc<<<dim3(1024, 9, BB), 256>>>(a, col);
    gemm_cp<<<dim3(16, 2, BB), 256, 147456>>>(col, KC, KC*4096LL, w1t, KC, 0LL,
        h, 256, CHW, KC, 1.f, conv1_b, gb, NUL, NUL, 0, 0LL, 0);

    gn_nhwc<<<BB*32, 256>>>(h, gn2_s, gn2_b, a, 1);
    im2col_nhwc<<<dim3(1024, 9, BB), 256>>>(a, col);
    gemm_cp<<<dim3(16, 2, BB), 256, 147456>>>(col, KC, KC*4096LL, w2t, KC, 0LL,
        xr, 256, CHW, KC, 1.f, conv2_b, NUL, NUL, xh, 256, CHW, 0);

    gn_nhwc<<<BB*32, 256>>>(xr, gnA_s, gnA_b, a, 0);
    gemm_cp<<<dim3(16, 6, BB), 256, 147456>>>(a, 256, CHW, qw, 256, 0LL,
        qkv, 768, 3*CHW, 256, 1.f, NUL, NUL, NUL, NUL, 0, 0LL, 1);
    gemm_cp<<<dim3(16, 32, BB), 256, 147456>>>(qkv, 768, 3*CHW, qkv + 256, 768, 3*CHW,
        S, 4096, SST, 256, 0.0625f, NUL, NUL, NUL, NUL, 0, 0LL, 0);
    softmax_row<<<dim3(4096, BB), 128>>>(S, rs);
    tr_kernel<<<dim3(128, 8, BB), tb>>>(qkv + 512, vt, 768, 4096, 3*CHW, CHW, 1);  // V->[d][t]
    gemm_cp<<<dim3(16, 2, BB), 256, 147456>>>(S, 4096, SST, vt, 4096, CHW,
        ao, 256, CHW, 4096, 1.f, NUL, NUL, rs, NUL, 0, 0LL, 1);
    gemm_cp<<<dim3(16, 2, BB), 256, 147456>>>(ao, 256, CHW, ow, 256, 0LL,
        tmp, 256, CHW, 256, 1.f, out_b, NUL, NUL, xr, 256, CHW, 0);
    tr_kernel<<<dim3(128, 8, BB), tb>>>(tmp, out, 256, 4096, CHW, CHW, 0);  // NHWC->NCHW
}

// round 7
// speedup vs baseline: 4.9785x; 1.3809x over previous
#include <cuda_runtime.h>
#include <cuda_bf16.h>
#include <math.h>

#define BB 4
#define CHW 1048576LL
#define SST 16777216LL
#define KC 2304

__device__ float g_xh [BB*CHW];
__device__ float g_a  [BB*CHW];
__device__ float g_h  [BB*CHW];
__device__ float g_xr [BB*CHW];
__device__ float g_ao [BB*CHW];
__device__ float g_tmp[BB*CHW];
__device__ float g_gb [BB*512];
__device__ float g_rs [BB*4096];
__device__ float g_w1t[256*KC];
__device__ float g_w2t[256*KC];
__device__ float g_qkvw[768*256];
__device__ float g_outw[256*256];
__device__ __nv_bfloat16 g_qkvb[BB*3*CHW];
__device__ __nv_bfloat16 g_vtb [BB*CHW];
__device__ __nv_bfloat16 g_Sb  [BB*SST];

__device__ __forceinline__ unsigned smem_u32(const void* p){
    unsigned r;
    asm("{ .reg .u64 t; cvta.to.shared.u64 t, %1; cvt.u32.u64 %0, t; }" : "=r"(r) : "l"(p));
    return r;
}
__device__ __forceinline__ float rnd_tf32(float f){
    unsigned r; asm("cvt.rna.tf32.f32 %0, %1;" : "=r"(r) : "f"(f));
    return __uint_as_float(r);
}
__device__ __forceinline__ unsigned swz(unsigned off){ return off ^ ((off >> 3) & 0x70u); }

#define LDMX4(r, addr) \
    asm volatile("ldmatrix.sync.aligned.m8n8.x4.shared.b16 {%0,%1,%2,%3}, [%4];" \
        : "=r"((r)[0]),"=r"((r)[1]),"=r"((r)[2]),"=r"((r)[3]) : "r"(addr))
#define MMAT(c, a, b0, b1) \
    asm volatile("mma.sync.aligned.m16n8k8.row.col.f32.tf32.tf32.f32 " \
        "{%0,%1,%2,%3},{%4,%5,%6,%7},{%8,%9},{%0,%1,%2,%3};" \
        : "+f"((c)[0]),"+f"((c)[1]),"+f"((c)[2]),"+f"((c)[3]) \
        : "r"((a)[0]),"r"((a)[1]),"r"((a)[2]),"r"((a)[3]),"r"(b0),"r"(b1))
#define MMAB(c, a, b0, b1) \
    asm volatile("mma.sync.aligned.m16n8k16.row.col.f32.bf16.bf16.f32 " \
        "{%0,%1,%2,%3},{%4,%5,%6,%7},{%8,%9},{%0,%1,%2,%3};" \
        : "+f"((c)[0]),"+f"((c)[1]),"+f"((c)[2]),"+f"((c)[3]) \
        : "r"((a)[0]),"r"((a)[1]),"r"((a)[2]),"r"((a)[3]),"r"(b0),"r"(b1))

// ============ tf32 GEMM, 256x128 tile, 3-stage cp.async; CONV=1 -> implicit im2col A ============
// D[b][m][n] = alpha*sum_k A[m][k]*B[n][k]; +bias; FiLM; +res. outMode: 0 float, 2 bf16.
template<int CONV>
__global__ void __launch_bounds__(256, 1) gemm_cp(
    const float* __restrict__ A, int lda, long long sA,
    const float* __restrict__ B, int ldb, long long sB,
    void* __restrict__ Yv, int ldy, long long sY,
    int K, float alpha,
    const float* __restrict__ bias, const float* __restrict__ film,
    const float* __restrict__ res, int ldr, long long sR, int outMode)
{
    extern __shared__ char smem[];
    unsigned sbase = smem_u32(smem);
    int tid = threadIdx.x, lane = tid & 31, wid = tid >> 5;
    int warp_m = wid & 3, warp_n = wid >> 2;
    int b = blockIdx.z;
    int m0 = blockIdx.x * 256, n0 = blockIdx.y * 128;
    const float* Ab = A + sA * b + (CONV ? 0 : (size_t)m0 * lda);
    const float* Bb = B + sB * b + (size_t)n0 * ldb;

    float acc[4][8][4];
    #pragma unroll
    for (int mi = 0; mi < 4; mi++)
        #pragma unroll
        for (int ni = 0; ni < 8; ni++)
            #pragma unroll
            for (int e = 0; e < 4; e++) acc[mi][ni][e] = 0.f;

#define ISSUE_T(st, kb) { \
    unsigned ab_ = sbase + (st) * 32768u; \
    unsigned bb_ = sbase + 98304u + (st) * 16384u; \
    if (CONV) { \
        int t_ = (kb) >> 3; int kh_ = t_ / 3 - 1; int kw_ = t_ - (t_ / 3) * 3 - 1; \
        int cb_ = ((kb) & 7) * 32; \
        _Pragma("unroll") \
        for (int i_ = 0; i_ < 8; i_++) { \
            int c_ = tid + i_ * 256; int row_ = c_ >> 3, seg_ = c_ & 7; \
            int p_ = m0 + row_; \
            int h2_ = (p_ >> 6) + kh_, w2_ = (p_ & 63) + kw_; \
            int ok_ = ((unsigned)h2_ < 64u) && ((unsigned)w2_ < 64u); \
            int hc_ = ok_ ? h2_ : 0, wc_ = ok_ ? w2_ : 0; \
            unsigned sz_ = ok_ ? 16u : 0u; \
            const float* src_ = Ab + (size_t)((hc_ << 6) + wc_) * 256 + cb_ + seg_ * 4; \
            unsigned d_ = ab_ + swz((unsigned)row_ * 128u + seg_ * 16u); \
            asm volatile("cp.async.cg.shared.global [%0], [%1], 16, %2;" :: "r"(d_), "l"(src_), "r"(sz_)); } \
    } else { \
        const float* As_ = Ab + (kb) * 32; \
        _Pragma("unroll") \
        for (int i_ = 0; i_ < 8; i_++) { \
            int c_ = tid + i_ * 256; int row_ = c_ >> 3, seg_ = c_ & 7; \
            unsigned d_ = ab_ + swz((unsigned)row_ * 128u + seg_ * 16u); \
            asm volatile("cp.async.cg.shared.global [%0], [%1], 16;" :: "r"(d_), "l"(As_ + (size_t)row_ * lda + seg_ * 4)); } \
    } \
    { const float* Bs_ = Bb + (kb) * 32; \
    _Pragma("unroll") \
    for (int i_ = 0; i_ < 4; i_++) { \
        int c_ = tid + i_ * 256; int row_ = c_ >> 3, seg_ = c_ & 7; \
        unsigned d_ = bb_ + swz((unsigned)row_ * 128u + seg_ * 16u); \
        asm volatile("cp.async.cg.shared.global [%0], [%1], 16;" :: "r"(d_), "l"(Bs_ + (size_t)row_ * ldb + seg_ * 4)); } } \
    asm volatile("cp.async.commit_group;"); }

    int nkb = K >> 5;
    ISSUE_T(0, 0);
    ISSUE_T(1, 1);

    unsigned arow = (unsigned)(warp_m * 64 + (lane & 7) + (lane & 8));
    unsigned acol = (lane & 16) ? 16u : 0u;
    unsigned brow = (unsigned)(warp_n * 64 + (lane & 7) + ((lane & 16) >> 1));
    unsigned bcol = (lane & 8) ? 16u : 0u;

    for (int kb = 0; kb < nkb; kb++) {
        int st = kb % 3;
        asm volatile("cp.async.wait_group 1;" ::: "memory");
        __syncthreads();
        unsigned ab_ = sbase + st * 32768u;
        unsigned bb_ = sbase + 98304u + st * 16384u;
        #pragma unroll
        for (int k8 = 0; k8 < 4; k8++) {
            unsigned kc = k8 * 32u;
            unsigned af[4][4], bf[4][4];
            #pragma unroll
            for (int mi = 0; mi < 4; mi++)
                LDMX4(af[mi], ab_ + swz((arow + mi * 16u) * 128u + kc + acol));
            #pragma unroll
            for (int pi = 0; pi < 4; pi++)
                LDMX4(bf[pi], bb_ + swz((brow + pi * 16u) * 128u + kc + bcol));
            #pragma unroll
            for (int mi = 0; mi < 4; mi++)
                #pragma unroll
                for (int pi = 0; pi < 4; pi++) {
                    MMAT(acc[mi][2*pi],   af[mi], bf[pi][0], bf[pi][1]);
                    MMAT(acc[mi][2*pi+1], af[mi], bf[pi][2], bf[pi][3]);
                }
        }
        if (kb + 2 < nkb) { ISSUE_T((kb + 2) % 3, kb + 2); }
        else asm volatile("cp.async.commit_group;");
    }

    int g = lane >> 2, t = lane & 3;
    #pragma unroll
    for (int mi = 0; mi < 4; mi++) {
        #pragma unroll
        for (int r = 0; r < 2; r++) {
            int m = m0 + warp_m * 64 + mi * 16 + g + r * 8;
            const float* Rr = res ? (res + sR * b + (size_t)m * ldr) : (const float*)0;
            #pragma unroll
            for (int ni = 0; ni < 8; ni++) {
                int n = n0 + warp_n * 64 + ni * 8 + 2 * t;
                float v0 = acc[mi][ni][2*r]     * alpha;
                float v1 = acc[mi][ni][2*r + 1] * alpha;
                if (bias) { v0 += bias[n]; v1 += bias[n + 1]; }
                if (film) {
                    const float* fg = film + (size_t)b * 512 + n;
                    v0 = (1.f + fg[0]) * v0 + fg[256];
                    v1 = (1.f + fg[1]) * v1 + fg[257];
                }
                if (Rr) { v0 += Rr[n]; v1 += Rr[n + 1]; }
                if (outMode == 2) {
                    __nv_bfloat16* Yb16 = (__nv_bfloat16*)Yv + sY * b + (size_t)m * ldy + n;
                    *(__nv_bfloat162*)Yb16 = __floats2bfloat162_rn(v0, v1);
                } else {
                    float* Yr = (float*)Yv + sY * b + (size_t)m * ldy;
                    *(float2*)&Yr[n] = make_float2(v0, v1);
                }
            }
        }
    }
}

// ============ bf16 GEMM, 256x128 tile, BK=64, 3-stage cp.async ============
// outMode: 1 float tf32-rounded (*rscale[m]), 2 bf16
__global__ void __launch_bounds__(256, 1) gemm_bf(
    const __nv_bfloat16* __restrict__ A, int lda, long long sA,
    const __nv_bfloat16* __restrict__ B, int ldb, long long sB,
    void* __restrict__ Yv, int ldy, long long sY,
    int K, float alpha, const float* __restrict__ rscale, int outMode)
{
    extern __shared__ char smem[];
    unsigned sbase = smem_u32(smem);
    int tid = threadIdx.x, lane = tid & 31, wid = tid >> 5;
    int warp_m = wid & 3, warp_n = wid >> 2;
    int b = blockIdx.z;
    int m0 = blockIdx.x * 256, n0 = blockIdx.y * 128;
    const __nv_bfloat16* Ab = A + sA * b + (size_t)m0 * lda;
    const __nv_bfloat16* Bb = B + sB * b + (size_t)n0 * ldb;

    float acc[4][8][4];
    #pragma unroll
    for (int mi = 0; mi < 4; mi++)
        #pragma unroll
        for (int ni = 0; ni < 8; ni++)
            #pragma unroll
            for (int e = 0; e < 4; e++) acc[mi][ni][e] = 0.f;

#define ISSUE_B(st, kb) { \
    unsigned ab_ = sbase + (st) * 32768u; \
    unsigned bb_ = sbase + 98304u + (st) * 16384u; \
    const __nv_bfloat16* As_ = Ab + (kb) * 64; \
    const __nv_bfloat16* Bs_ = Bb + (kb) * 64; \
    _Pragma("unroll") \
    for (int i_ = 0; i_ < 8; i_++) { \
        int c_ = tid + i_ * 256; int row_ = c_ >> 3, seg_ = c_ & 7; \
        unsigned d_ = ab_ + swz((unsigned)row_ * 128u + seg_ * 16u); \
        asm volatile("cp.async.cg.shared.global [%0], [%1], 16;" :: "r"(d_), "l"(As_ + (size_t)row_ * lda + seg_ * 8)); } \
    _Pragma("unroll") \
    for (int i_ = 0; i_ < 4; i_++) { \
        int c_ = tid + i_ * 256; int row_ = c_ >> 3, seg_ = c_ & 7; \
        unsigned d_ = bb_ + swz((unsigned)row_ * 128u + seg_ * 16u); \
        asm volatile("cp.async.cg.shared.global [%0], [%1], 16;" :: "r"(d_), "l"(Bs_ + (size_t)row_ * ldb + seg_ * 8)); } \
    asm volatile("cp.async.commit_group;"); }

    int nkb = K >> 6;
    ISSUE_B(0, 0);
    ISSUE_B(1, 1);

    unsigned arow = (unsigned)(warp_m * 64 + (lane & 7) + (lane & 8));
    unsigned acol = (lane & 16) ? 16u : 0u;
    unsigned brow = (unsigned)(warp_n * 64 + (lane & 7) + ((lane & 16) >> 1));
    unsigned bcol = (lane & 8) ? 16u : 0u;

    for (int kb = 0; kb < nkb; kb++) {
        int st = kb % 3;
        asm volatile("cp.async.wait_group 1;" ::: "memory");
        __syncthreads();
        unsigned ab_ = sbase + st * 32768u;
        unsigned bb_ = sbase + 98304u + st * 16384u;
        #pragma unroll
        for (int k16 = 0; k16 < 4; k16++) {
            unsigned kc = k16 * 32u;
            unsigned af[4][4], bf[4][4];
            #pragma unroll
            for (int mi = 0; mi < 4; mi++)
                LDMX4(af[mi], ab_ + swz((arow + mi * 16u) * 128u + kc + acol));
            #pragma unroll
            for (int pi = 0; pi < 4; pi++)
                LDMX4(bf[pi], bb_ + swz((brow + pi * 16u) * 128u + kc + bcol));
            #pragma unroll
            for (int mi = 0; mi < 4; mi++)
                #pragma unroll
                for (int pi = 0; pi < 4; pi++) {
                    MMAB(acc[mi][2*pi],   af[mi], bf[pi][0], bf[pi][1]);
                    MMAB(acc[mi][2*pi+1], af[mi], bf[pi][2], bf[pi][3]);
                }
        }
        if (kb + 2 < nkb) { ISSUE_B((kb + 2) % 3, kb + 2); }
        else asm volatile("cp.async.commit_group;");
    }

    int g = lane >> 2, t = lane & 3;
    #pragma unroll
    for (int mi = 0; mi < 4; mi++) {
        #pragma unroll
        for (int r = 0; r < 2; r++) {
            int m = m0 + warp_m * 64 + mi * 16 + g + r * 8;
            float rsv = rscale ? rscale[(size_t)b * 4096 + m] : 1.f;
            #pragma unroll
            for (int ni = 0; ni < 8; ni++) {
                int n = n0 + warp_n * 64 + ni * 8 + 2 * t;
                float v0 = acc[mi][ni][2*r]     * alpha * rsv;
                float v1 = acc[mi][ni][2*r + 1] * alpha * rsv;
                if (outMode == 2) {
                    __nv_bfloat16* Yb16 = (__nv_bfloat16*)Yv + sY * b + (size_t)m * ldy + n;
                    *(__nv_bfloat162*)Yb16 = __floats2bfloat162_rn(v0, v1);
                } else {
                    float* Yr = (float*)Yv + sY * b + (size_t)m * ldy;
                    *(float2*)&Yr[n] = make_float2(rnd_tf32(v0), rnd_tf32(v1));
                }
            }
        }
    }
}

// out[b][j][i] = in[b][i][j]; grid (I/32, J/32, BB), block (32,8)
__global__ void tr_kernel(const float* __restrict__ in, float* __restrict__ out,
                          int ldin, int ldout, long long sIn, long long sOut) {
    __shared__ float t[32][33];
    int i0 = blockIdx.x * 32, j0 = blockIdx.y * 32, b = blockIdx.z;
    int tx = threadIdx.x, ty = threadIdx.y;
    #pragma unroll
    for (int r = 0; r < 4; r++)
        t[ty + r*8][tx] = in[sIn*b + (size_t)(i0 + ty + r*8) * ldin + j0 + tx];
    __syncthreads();
    #pragma unroll
    for (int r = 0; r < 4; r++)
        out[sOut*b + (size_t)(j0 + ty + r*8) * ldout + i0 + tx] = t[tx][ty + r*8];
}

// V transpose bf16: vtb[b][d][t] = qkvb[b][t][512+d]; grid (128, 8, BB), block (32,8)
__global__ void trb_kernel(const __nv_bfloat16* __restrict__ in, __nv_bfloat16* __restrict__ out) {
    __shared__ unsigned short t[32][33];
    int i0 = blockIdx.x * 32, j0 = blockIdx.y * 32, b = blockIdx.z;
    int tx = threadIdx.x, ty = threadIdx.y;
    const unsigned short* ip = (const unsigned short*)(in + (size_t)b * 3 * CHW);
    unsigned short* op = (unsigned short*)(out + (size_t)b * CHW);
    #pragma unroll
    for (int r = 0; r < 4; r++)
        t[ty + r*8][tx] = ip[(size_t)(i0 + ty + r*8) * 768 + 512 + j0 + tx];
    __syncthreads();
    #pragma unroll
    for (int r = 0; r < 4; r++)
        op[(size_t)(j0 + ty + r*8) * 4096 + i0 + tx] = t[tx][ty + r*8];
}

// GroupNorm NHWC (+opt SiLU), tf32-rounded out; grid BB*32, block 256
__global__ void gn_nhwc(const float* __restrict__ x, const float* __restrict__ sc,
                        const float* __restrict__ bi, float* __restrict__ y, int dosilu) {
    __shared__ float rsh[256], rqh[256], mv[2];
    int b = blockIdx.x >> 5, g = blockIdx.x & 31;
    const float* xp = x + (size_t)b * CHW + g * 8;
    float* yp = y + (size_t)b * CHW + g * 8;
    int tid = threadIdx.x;
    float sum = 0.f, sq = 0.f;
    for (int i = tid; i < 4096; i += 256) {
        float4 v0 = *(const float4*)&xp[(size_t)i * 256];
        float4 v1 = *(const float4*)&xp[(size_t)i * 256 + 4];
        sum += (v0.x+v0.y)+(v0.z+v0.w)+(v1.x+v1.y)+(v1.z+v1.w);
        sq += v0.x*v0.x+v0.y*v0.y+v0.z*v0.z+v0.w*v0.w+v1.x*v1.x+v1.y*v1.y+v1.z*v1.z+v1.w*v1.w;
    }
    rsh[tid] = sum; rqh[tid] = sq;
    __syncthreads();
    for (int st = 128; st > 0; st >>= 1) {
        if (tid < st) { rsh[tid] += rsh[tid+st]; rqh[tid] += rqh[tid+st]; }
        __syncthreads();
    }
    if (tid == 0) {
        float m = rsh[0] * (1.f/32768.f);
        mv[0] = m; mv[1] = rsqrtf(rqh[0] * (1.f/32768.f) - m*m + 1e-5f);
    }
    __syncthreads();
    float m = mv[0], inv = mv[1], aa[8], bb[8];
    #pragma unroll
    for (int j = 0; j < 8; j++) { aa[j] = inv * sc[g*8+j]; bb[j] = bi[g*8+j] - m * aa[j]; }
    for (int i = tid; i < 4096; i += 256) {
        float4 v0 = *(const float4*)&xp[(size_t)i * 256];
        float4 v1 = *(const float4*)&xp[(size_t)i * 256 + 4];
        float v[8] = { v0.x,v0.y,v0.z,v0.w,v1.x,v1.y,v1.z,v1.w };
        #pragma unroll
        for (int j = 0; j < 8; j++) {
            float tv = v[j]*aa[j] + bb[j];
            if (dosilu) tv = tv / (1.f + __expf(-tv));
            v[j] = rnd_tf32(tv);
        }
        *(float4*)&yp[(size_t)i*256]   = make_float4(v[0],v[1],v[2],v[3]);
        *(float4*)&yp[(size_t)i*256+4] = make_float4(v[4],v[5],v[6],v[7]);
    }
}

// wt[o][t*256+ic] = round(w[o][ic*9+t]); grid (9, 256), block 256
__global__ void wtrans(const float* __restrict__ w, float* __restrict__ wt) {
    int o = blockIdx.y;
    int ko = blockIdx.x * 256 + threadIdx.x;
    wt[(size_t)o * KC + ko] = rnd_tf32(w[(size_t)o * KC + (ko & 255) * 9 + (ko >> 8)]);
}

__global__ void round_copy(const float* __restrict__ in, float* __restrict__ out, int n) {
    int i = blockIdx.x * 256 + threadIdx.x;
    if (i < n) out[i] = rnd_tf32(in[i]);
}

// grid (BB, 4), block 128
__global__ void film_mlp(const float* __restrict__ te, const float* __restrict__ w,
                         const float* __restrict__ bi, float* __restrict__ gb) {
    __shared__ float s_te[256];
    int b = blockIdx.x, tid = threadIdx.x;
    for (int i = tid; i < 256; i += 128) {
        float v = te[b * 256 + i];
        s_te[i] = v / (1.f + __expf(-v));
    }
    __syncthreads();
    int j = blockIdx.y * 128 + tid;
    const float* wr = w + (size_t)j * 256;
    float acc = bi[j];
    for (int t = 0; t < 256; t++) acc += s_te[t] * wr[t];
    gb[b * 512 + j] = acc;
}

// row softmax on bf16 S; 1/sum -> rs; grid (4096, BB), block 128
__global__ void softmax_bf(__nv_bfloat16* __restrict__ S, float* __restrict__ rs) {
    __shared__ float red[4];
    uint4* p = (uint4*)(S + (size_t)blockIdx.y * SST + (size_t)blockIdx.x * 4096);
    int tid = threadIdx.x, lane = tid & 31, wid = tid >> 5;
    uint4 v[4];
    float mx = -1e30f;
    #pragma unroll
    for (int k = 0; k < 4; k++) {
        v[k] = p[tid + k * 128];
        __nv_bfloat162* pv = (__nv_bfloat162*)&v[k];
        #pragma unroll
        for (int j = 0; j < 4; j++) {
            float2 f = __bfloat1622float2(pv[j]);
            mx = fmaxf(mx, fmaxf(f.x, f.y));
        }
    }
    #pragma unroll
    for (int o = 16; o; o >>= 1) mx = fmaxf(mx, __shfl_xor_sync(~0u, mx, o));
    if (lane == 0) red[wid] = mx;
    __syncthreads();
    mx = fmaxf(fmaxf(red[0], red[1]), fmaxf(red[2], red[3]));
    __syncthreads();
    float sm = 0.f;
    #pragma unroll
    for (int k = 0; k < 4; k++) {
        __nv_bfloat162* pv = (__nv_bfloat162*)&v[k];
        #pragma unroll
        for (int j = 0; j < 4; j++) {
            float2 f = __bfloat1622float2(pv[j]);
            f.x = __expf(f.x - mx); f.y = __expf(f.y - mx);
            sm += f.x + f.y;
            pv[j] = __floats2bfloat162_rn(f.x, f.y);
        }
        p[tid + k * 128] = v[k];
    }
    #pragma unroll
    for (int o = 16; o; o >>= 1) sm += __shfl_xor_sync(~0u, sm, o);
    if (lane == 0) red[wid] = sm;
    __syncthreads();
    if (tid == 0)
        rs[(size_t)blockIdx.y * 4096 + blockIdx.x] = 1.f / (red[0]+red[1]+red[2]+red[3]);
}

extern "C" void kernel_launch(void* const* d_in, const int* in_sizes, int n_in,
                              void* d_out, int out_size) {
    const float* x = (const float*)d_in[0];
    const float* te = (const float*)d_in[1];
    const float* gn1_s = (const float*)d_in[2];
    const float* gn1_b = (const float*)d_in[3];
    const float* conv1_w = (const float*)d_in[4];
    const float* conv1_b = (const float*)d_in[5];
    const float* mlp_w = (const float*)d_in[6];
    const float* mlp_b = (const float*)d_in[7];
    const float* gn2_s = (const float*)d_in[8];
    const float* gn2_b = (const float*)d_in[9];
    const float* conv2_w = (const float*)d_in[10];
    const float* conv2_b = (const float*)d_in[11];
    const float* gnA_s = (const float*)d_in[12];
    const float* gnA_b = (const float*)d_in[13];
    const float* qkv_w = (const float*)d_in[14];
    const float* out_w = (const float*)d_in[15];
    const float* out_b = (const float*)d_in[16];
    float* out = (float*)d_out;

    float *xh,*a,*h,*xr,*ao,*tmp,*gb,*rs,*w1t,*w2t,*qw,*ow;
    __nv_bfloat16 *qkvb,*vtb,*Sb;
    cudaGetSymbolAddress((void**)&xh, g_xh);  cudaGetSymbolAddress((void**)&a, g_a);
    cudaGetSymbolAddress((void**)&h, g_h);    cudaGetSymbolAddress((void**)&xr, g_xr);
    cudaGetSymbolAddress((void**)&ao, g_ao);  cudaGetSymbolAddress((void**)&tmp, g_tmp);
    cudaGetSymbolAddress((void**)&gb, g_gb);  cudaGetSymbolAddress((void**)&rs, g_rs);
    cudaGetSymbolAddress((void**)&w1t, g_w1t);cudaGetSymbolAddress((void**)&w2t, g_w2t);
    cudaGetSymbolAddress((void**)&qw, g_qkvw);cudaGetSymbolAddress((void**)&ow, g_outw);
    cudaGetSymbolAddress((void**)&qkvb, g_qkvb);
    cudaGetSymbolAddress((void**)&vtb, g_vtb);
    cudaGetSymbolAddress((void**)&Sb, g_Sb);

    static int init_done = 0;
    if (!init_done) {
        cudaFuncSetAttribute(gemm_cp<0>, cudaFuncAttributeMaxDynamicSharedMemorySize, 147456);
        cudaFuncSetAttribute(gemm_cp<1>, cudaFuncAttributeMaxDynamicSharedMemorySize, 147456);
        cudaFuncSetAttribute(gemm_bf, cudaFuncAttributeMaxDynamicSharedMemorySize, 147456);
        init_done = 1;
    }
    const float* NUL = (const float*)0;
    dim3 tb(32, 8);

    film_mlp<<<dim3(BB, 4), 128>>>(te, mlp_w, mlp_b, gb);
    wtrans<<<dim3(9, 256), 256>>>(conv1_w, w1t);
    wtrans<<<dim3(9, 256), 256>>>(conv2_w, w2t);
    round_copy<<<768, 256>>>(qkv_w, qw, 768 * 256);
    round_copy<<<256, 256>>>(out_w, ow, 256 * 256);
    tr_kernel<<<dim3(8, 128, BB), tb>>>(x, xh, 4096, 256, CHW, CHW);   // NCHW->NHWC

    // conv1 (implicit im2col) + FiLM
    gn_nhwc<<<BB*32, 256>>>(xh, gn1_s, gn1_b, a, 1);
    gemm_cp<1><<<dim3(16, 2, BB), 256, 147456>>>(a, 256, CHW, w1t, KC, 0LL,
        h, 256, CHW, KC, 1.f, conv1_b, gb, NUL, 0, 0LL, 0);

    // conv2 + x residual
    gn_nhwc<<<BB*32, 256>>>(h, gn2_s, gn2_b, a, 1);
    gemm_cp<1><<<dim3(16, 2, BB), 256, 147456>>>(a, 256, CHW, w2t, KC, 0LL,
        xr, 256, CHW, KC, 1.f, conv2_b, NUL, xh, 256, CHW, 0);

    // attention
    gn_nhwc<<<BB*32, 256>>>(xr, gnA_s, gnA_b, a, 0);
    gemm_cp<0><<<dim3(16, 6, BB), 256, 147456>>>(a, 256, CHW, qw, 256, 0LL,
        qkvb, 768, 3*CHW, 256, 1.f, NUL, NUL, NUL, 0, 0LL, 2);
    trb_kernel<<<dim3(128, 8, BB), tb>>>(qkvb, vtb);
    gemm_bf<<<dim3(16, 32, BB), 256, 147456>>>(qkvb, 768, 3*CHW, qkvb + 256, 768, 3*CHW,
        Sb, 4096, SST, 256, 0.0625f, NUL, 2);
    softmax_bf<<<dim3(4096, BB), 128>>>(Sb, rs);
    gemm_bf<<<dim3(16, 2, BB), 256, 147456>>>(Sb, 4096, SST, vtb, 4096, CHW,
        ao, 256, CHW, 4096, 1.f, rs, 1);
    gemm_cp<0><<<dim3(16, 2, BB), 256, 147456>>>(ao, 256, CHW, ow, 256, 0LL,
        tmp, 256, CHW, 256, 1.f, out_b, NUL, xr, 256, CHW, 0);
    tr_kernel<<<dim3(128, 8, BB), tb>>>(tmp, out, 256, 4096, CHW, CHW);  // NHWC->NCHW
}